// round 16
// baseline (speedup 1.0000x reference)
#include <cuda_runtime.h>
#include <cuda_bf16.h>
#include <stdint.h>
#include <math_constants.h>

#define BATCH 2
#define SEQ   2048
#define EMB   1024
#define NH    16
#define HD    64
#define TOK   4096
#define QKVF  3072
#define NROWS (BATCH * NH * SEQ)
#define OUT_ELEMS ((size_t)TOK * EMB)

__device__ float g_qkv[(size_t)TOK * QKVF];   // 50 MB scratch
__device__ float g_ao [(size_t)TOK * EMB];    // 16 MB scratch
__device__ float g_rowsum[NROWS];

// ---------------------------------------------------------------------------
// helpers
// ---------------------------------------------------------------------------
__device__ __forceinline__ void mma_bf16(float* c, const uint32_t* a, uint32_t b0, uint32_t b1) {
    asm volatile(
        "mma.sync.aligned.m16n8k16.row.col.f32.bf16.bf16.f32 "
        "{%0,%1,%2,%3}, {%4,%5,%6,%7}, {%8,%9}, {%0,%1,%2,%3};"
        : "+f"(c[0]), "+f"(c[1]), "+f"(c[2]), "+f"(c[3])
        : "r"(a[0]), "r"(a[1]), "r"(a[2]), "r"(a[3]), "r"(b0), "r"(b1));
}

__device__ __forceinline__ void split2(float x, float y, uint32_t& hi, uint32_t& lo) {
    __nv_bfloat16 bx = __float2bfloat16_rn(x), by = __float2bfloat16_rn(y);
    float rx = x - __bfloat162float(bx);
    float ry = y - __bfloat162float(by);
    __nv_bfloat162 h; h.x = bx; h.y = by;
    __nv_bfloat162 l = __floats2bfloat162_rn(rx, ry);
    hi = *reinterpret_cast<uint32_t*>(&h);
    lo = *reinterpret_cast<uint32_t*>(&l);
}

#define STRB 80          // smem row stride bytes: 64B data + 16B pad (bank-clean)
#define BUF128 (128 * STRB)
#define BUF64  (64 * STRB)

__global__ void zero_rowsum_kernel() {
    g_rowsum[blockIdx.x * 256 + threadIdx.x] = 0.f;
}

// ---------------------------------------------------------------------------
// C[M,N] = A[M,K] @ W[N,K]^T + bias.  Block 128x128, BK=32, 8 warps (2x4).
// Single-buffer smem, 3 CTAs/SM pinned.
// ---------------------------------------------------------------------------
__global__ void __launch_bounds__(256, 3) mma_gemm_bias(
    const float* __restrict__ A, const float* __restrict__ W,
    const float* __restrict__ bias, float* __restrict__ C, int N, int K)
{
    __shared__ __align__(16) char sAh[BUF128];
    __shared__ __align__(16) char sAl[BUF128];
    __shared__ __align__(16) char sBh[BUF128];
    __shared__ __align__(16) char sBl[BUF128];

    const int tid = threadIdx.x;
    const int lane = tid & 31, wid = tid >> 5;
    const int warp_m = wid >> 2, warp_n = wid & 3;
    const int bm = blockIdx.y * 128, bn = blockIdx.x * 128;
    const int row = tid >> 1, kq = (tid & 1) * 16;
    const int r4 = lane >> 2, c4 = lane & 3;

    float acc[4][4][4];
#pragma unroll
    for (int i = 0; i < 4; i++)
#pragma unroll
        for (int j = 0; j < 4; j++)
#pragma unroll
            for (int l = 0; l < 4; l++) acc[i][j][l] = 0.f;

    for (int kt = 0; kt < (K >> 5); kt++) {
        const float* Ap = A + (size_t)(bm + row) * K + kt * 32 + kq;
        const float* Wp = W + (size_t)(bn + row) * K + kt * 32 + kq;
        float4 av[4], wv[4];
#pragma unroll
        for (int i = 0; i < 4; i++) av[i] = *(const float4*)(Ap + i * 4);
#pragma unroll
        for (int i = 0; i < 4; i++) wv[i] = *(const float4*)(Wp + i * 4);
        __syncthreads();
#pragma unroll
        for (int i = 0; i < 4; i++) {
            uint32_t h0, l0, h1, l1;
            split2(av[i].x, av[i].y, h0, l0);
            split2(av[i].z, av[i].w, h1, l1);
            uint32_t off = row * STRB + (kq + i * 4) * 2;
            *(uint2*)(sAh + off) = make_uint2(h0, h1);
            *(uint2*)(sAl + off) = make_uint2(l0, l1);
            split2(wv[i].x, wv[i].y, h0, l0);
            split2(wv[i].z, wv[i].w, h1, l1);
            *(uint2*)(sBh + off) = make_uint2(h0, h1);
            *(uint2*)(sBl + off) = make_uint2(l0, l1);
        }
        __syncthreads();

#pragma unroll
        for (int s = 0; s < 2; s++) {
            const int kb = s * 32;
            uint32_t Ah[4][4], Al[4][4];
#pragma unroll
            for (int fm = 0; fm < 4; fm++) {
                uint32_t base = (warp_m * 64 + fm * 16 + r4) * STRB + kb + c4 * 4;
                Ah[fm][0] = *(const uint32_t*)(sAh + base);
                Ah[fm][1] = *(const uint32_t*)(sAh + base + 8 * STRB);
                Ah[fm][2] = *(const uint32_t*)(sAh + base + 16);
                Ah[fm][3] = *(const uint32_t*)(sAh + base + 8 * STRB + 16);
                Al[fm][0] = *(const uint32_t*)(sAl + base);
                Al[fm][1] = *(const uint32_t*)(sAl + base + 8 * STRB);
                Al[fm][2] = *(const uint32_t*)(sAl + base + 16);
                Al[fm][3] = *(const uint32_t*)(sAl + base + 8 * STRB + 16);
            }
#pragma unroll
            for (int fn = 0; fn < 4; fn++) {
                uint32_t bb = (warp_n * 32 + fn * 8 + r4) * STRB + kb + c4 * 4;
                uint32_t Bh0 = *(const uint32_t*)(sBh + bb);
                uint32_t Bh1 = *(const uint32_t*)(sBh + bb + 16);
                uint32_t Bl0 = *(const uint32_t*)(sBl + bb);
                uint32_t Bl1 = *(const uint32_t*)(sBl + bb + 16);
#pragma unroll
                for (int fm = 0; fm < 4; fm++) {
                    mma_bf16(acc[fm][fn], Ah[fm], Bh0, Bh1);
                    mma_bf16(acc[fm][fn], Ah[fm], Bl0, Bl1);
                    mma_bf16(acc[fm][fn], Al[fm], Bh0, Bh1);
                }
            }
        }
    }

    const int cq = c4 * 2;
#pragma unroll
    for (int fm = 0; fm < 4; fm++) {
#pragma unroll
        for (int fn = 0; fn < 4; fn++) {
            int row0 = bm + warp_m * 64 + fm * 16 + r4;
            int col  = bn + warp_n * 32 + fn * 8 + cq;
            float b0 = bias[col], b1 = bias[col + 1];
            *(float2*)(C + (size_t)row0 * N + col) =
                make_float2(acc[fm][fn][0] + b0, acc[fm][fn][1] + b1);
            *(float2*)(C + (size_t)(row0 + 8) * N + col) =
                make_float2(acc[fm][fn][2] + b0, acc[fm][fn][3] + b1);
        }
    }
}

// ---------------------------------------------------------------------------
// Scores + exp: E = exp(0.125 * Q K^T), atomic row sums.
// ---------------------------------------------------------------------------
__global__ void __launch_bounds__(256) mma_scores_exp(
    const float* __restrict__ qkv, float* __restrict__ attn)
{
    __shared__ __align__(16) char sAh[BUF128];
    __shared__ __align__(16) char sAl[BUF128];
    __shared__ __align__(16) char sBh[BUF128];
    __shared__ __align__(16) char sBl[BUF128];

    const int tid = threadIdx.x;
    const int lane = tid & 31, wid = tid >> 5;
    const int warp_m = wid >> 2, warp_n = wid & 3;
    const int z = blockIdx.z, b = z >> 4, h = z & 15;
    const int bm = blockIdx.y * 128, bn = blockIdx.x * 128;
    const float* Qb = qkv + (size_t)b * SEQ * QKVF + h * HD;
    const float* Kb = Qb + EMB;
    float* Cb = attn + (size_t)z * SEQ * SEQ;
    const int row = tid >> 1, kq = (tid & 1) * 16;
    const int r4 = lane >> 2, c4 = lane & 3;

    float acc[4][4][4];
#pragma unroll
    for (int i = 0; i < 4; i++)
#pragma unroll
        for (int j = 0; j < 4; j++)
#pragma unroll
            for (int l = 0; l < 4; l++) acc[i][j][l] = 0.f;

#pragma unroll
    for (int kt = 0; kt < 2; kt++) {
        const float* Ap = Qb + (size_t)(bm + row) * QKVF + kt * 32 + kq;
        const float* Bp = Kb + (size_t)(bn + row) * QKVF + kt * 32 + kq;
        float4 av[4], wv[4];
#pragma unroll
        for (int i = 0; i < 4; i++) av[i] = *(const float4*)(Ap + i * 4);
#pragma unroll
        for (int i = 0; i < 4; i++) wv[i] = *(const float4*)(Bp + i * 4);
        __syncthreads();
#pragma unroll
        for (int i = 0; i < 4; i++) {
            uint32_t h0, l0, h1, l1;
            split2(av[i].x, av[i].y, h0, l0);
            split2(av[i].z, av[i].w, h1, l1);
            uint32_t off = row * STRB + (kq + i * 4) * 2;
            *(uint2*)(sAh + off) = make_uint2(h0, h1);
            *(uint2*)(sAl + off) = make_uint2(l0, l1);
            split2(wv[i].x, wv[i].y, h0, l0);
            split2(wv[i].z, wv[i].w, h1, l1);
            *(uint2*)(sBh + off) = make_uint2(h0, h1);
            *(uint2*)(sBl + off) = make_uint2(l0, l1);
        }
        __syncthreads();

#pragma unroll
        for (int s = 0; s < 2; s++) {
            const int kb = s * 32;
            uint32_t Ah[4][4], Al[4][4];
#pragma unroll
            for (int fm = 0; fm < 4; fm++) {
                uint32_t base = (warp_m * 64 + fm * 16 + r4) * STRB + kb + c4 * 4;
                Ah[fm][0] = *(const uint32_t*)(sAh + base);
                Ah[fm][1] = *(const uint32_t*)(sAh + base + 8 * STRB);
                Ah[fm][2] = *(const uint32_t*)(sAh + base + 16);
                Ah[fm][3] = *(const uint32_t*)(sAh + base + 8 * STRB + 16);
                Al[fm][0] = *(const uint32_t*)(sAl + base);
                Al[fm][1] = *(const uint32_t*)(sAl + base + 8 * STRB);
                Al[fm][2] = *(const uint32_t*)(sAl + base + 16);
                Al[fm][3] = *(const uint32_t*)(sAl + base + 8 * STRB + 16);
            }
#pragma unroll
            for (int fn = 0; fn < 4; fn++) {
                uint32_t bb = (warp_n * 32 + fn * 8 + r4) * STRB + kb + c4 * 4;
                uint32_t Bh0 = *(const uint32_t*)(sBh + bb);
                uint32_t Bh1 = *(const uint32_t*)(sBh + bb + 16);
                uint32_t Bl0 = *(const uint32_t*)(sBl + bb);
                uint32_t Bl1 = *(const uint32_t*)(sBl + bb + 16);
#pragma unroll
                for (int fm = 0; fm < 4; fm++) {
                    mma_bf16(acc[fm][fn], Ah[fm], Bh0, Bh1);
                    mma_bf16(acc[fm][fn], Ah[fm], Bl0, Bl1);
                    mma_bf16(acc[fm][fn], Al[fm], Bh0, Bh1);
                }
            }
        }
    }

    // epilogue: exp, store E, row-sum atomics
#pragma unroll
    for (int fm = 0; fm < 4; fm++) {
        const int row0 = bm + warp_m * 64 + fm * 16 + r4;
        float rs0 = 0.f, rs1 = 0.f;
#pragma unroll
        for (int fn = 0; fn < 4; fn++) {
            float e0 = __expf(acc[fm][fn][0] * 0.125f);
            float e1 = __expf(acc[fm][fn][1] * 0.125f);
            float e2 = __expf(acc[fm][fn][2] * 0.125f);
            float e3 = __expf(acc[fm][fn][3] * 0.125f);
            rs0 += e0 + e1;
            rs1 += e2 + e3;
            int col = bn + warp_n * 32 + fn * 8 + c4 * 2;
            *(float2*)(Cb + (size_t)row0 * SEQ + col)       = make_float2(e0, e1);
            *(float2*)(Cb + (size_t)(row0 + 8) * SEQ + col) = make_float2(e2, e3);
        }
        rs0 += __shfl_xor_sync(0xffffffffu, rs0, 1);
        rs0 += __shfl_xor_sync(0xffffffffu, rs0, 2);
        rs1 += __shfl_xor_sync(0xffffffffu, rs1, 1);
        rs1 += __shfl_xor_sync(0xffffffffu, rs1, 2);
        if (c4 == 0) {
            atomicAdd(&g_rowsum[(size_t)z * SEQ + row0], rs0);
            atomicAdd(&g_rowsum[(size_t)z * SEQ + row0 + 8], rs1);
        }
    }
}

// ---------------------------------------------------------------------------
// AV + normalize, double-buffered on the P stream (DRAM-unique); V loaded
// per-tile at staging time (L2-resident, shared by 16 CTAs). P writeback
// after the MMA section. Block 128x64, BK=32, 8 warps (4x2), 3 CTAs/SM.
// ---------------------------------------------------------------------------
__global__ void __launch_bounds__(256, 3) mma_av_norm(
    float* __restrict__ attn, const float* __restrict__ qkv,
    float* __restrict__ out)
{
    __shared__ __align__(16) char sAh[2 * BUF128];
    __shared__ __align__(16) char sAl[2 * BUF128];
    __shared__ __align__(16) char sBh[2 * BUF64];
    __shared__ __align__(16) char sBl[2 * BUF64];

    const int tid = threadIdx.x;
    const int lane = tid & 31, wid = tid >> 5;
    const int warp_m = wid >> 1, warp_n = wid & 1;
    const int z = blockIdx.y, b = z >> 4, h = z & 15;
    const int bm = blockIdx.x * 128;
    float* P = attn + (size_t)z * SEQ * SEQ;
    const float* V = qkv + (size_t)b * SEQ * QKVF + 2 * EMB + h * HD;
    float* O = out + (size_t)b * SEQ * EMB + h * HD;
    const int row = tid >> 1, kq = (tid & 1) * 16;
    const int vt2 = tid & 15;            // t-pair index: rows 2*vt2, 2*vt2+1
    const int vd4 = (tid >> 4) * 4;      // d base (0..60 step 4)
    const int r4 = lane >> 2, c4 = lane & 3;

    const float inv_l = __frcp_rn(g_rowsum[(size_t)z * SEQ + bm + row]);

    float acc[2][4][4];
#pragma unroll
    for (int i = 0; i < 2; i++)
#pragma unroll
        for (int j = 0; j < 4; j++)
#pragma unroll
            for (int l = 0; l < 4; l++) acc[i][j][l] = 0.f;

    float* Pb = P + (size_t)(bm + row) * SEQ + kq;
    const float* Vb0 = V + (size_t)(2 * vt2) * QKVF + vd4;
    const float* Vb1 = V + (size_t)(2 * vt2 + 1) * QKVF + vd4;

    // prologue: tile 0 — load raw E, normalize, write P back
    float4 av[4];
#pragma unroll
    for (int i = 0; i < 4; i++) {
        av[i] = *(const float4*)(Pb + i * 4);
        av[i].x *= inv_l; av[i].y *= inv_l; av[i].z *= inv_l; av[i].w *= inv_l;
    }
#pragma unroll
    for (int i = 0; i < 4; i++) *(float4*)(Pb + i * 4) = av[i];

    const int NIT = SEQ >> 5;
    for (int kt = 0; kt < NIT; kt++) {
        char* bAh = sAh + (kt & 1) * BUF128;
        char* bAl = sAl + (kt & 1) * BUF128;
        char* bBh = sBh + (kt & 1) * BUF64;
        char* bBl = sBl + (kt & 1) * BUF64;
        // V for THIS tile (L2-hot; issue early in the staging phase)
        float4 v0 = *(const float4*)(Vb0 + (size_t)kt * 32 * QKVF);
        float4 v1 = *(const float4*)(Vb1 + (size_t)kt * 32 * QKVF);
        // stage A (normalized P, prefetched)
#pragma unroll
        for (int i = 0; i < 4; i++) {
            uint32_t h0, l0, h1, l1;
            split2(av[i].x, av[i].y, h0, l0);
            split2(av[i].z, av[i].w, h1, l1);
            uint32_t off = row * STRB + (kq + i * 4) * 2;
            *(uint2*)(bAh + off) = make_uint2(h0, h1);
            *(uint2*)(bAl + off) = make_uint2(l0, l1);
        }
        // stage V pair-packed: sB[d][t-pair]
        {
            float a0[4] = {v0.x, v0.y, v0.z, v0.w};
            float a1[4] = {v1.x, v1.y, v1.z, v1.w};
#pragma unroll
            for (int j = 0; j < 4; j++) {
                int d = vd4 + j;
                __nv_bfloat16 h0 = __float2bfloat16_rn(a0[j]);
                __nv_bfloat16 h1 = __float2bfloat16_rn(a1[j]);
                __nv_bfloat162 hp; hp.x = h0; hp.y = h1;
                __nv_bfloat162 lp = __floats2bfloat162_rn(
                    a0[j] - __bfloat162float(h0), a1[j] - __bfloat162float(h1));
                *(uint32_t*)(bBh + d * STRB + vt2 * 4) = *reinterpret_cast<uint32_t*>(&hp);
                *(uint32_t*)(bBl + d * STRB + vt2 * 4) = *reinterpret_cast<uint32_t*>(&lp);
            }
        }
        __syncthreads();

        // prefetch next P tile (raw E — scaled after MMAs)
        if (kt + 1 < NIT) {
#pragma unroll
            for (int i = 0; i < 4; i++) av[i] = *(const float4*)(Pb + (kt + 1) * 32 + i * 4);
        }

#pragma unroll
        for (int s = 0; s < 2; s++) {
            const int kb = s * 32;
            uint32_t Ah[2][4], Al[2][4];
#pragma unroll
            for (int fm = 0; fm < 2; fm++) {
                uint32_t base = (warp_m * 32 + fm * 16 + r4) * STRB + kb + c4 * 4;
                Ah[fm][0] = *(const uint32_t*)(bAh + base);
                Ah[fm][1] = *(const uint32_t*)(bAh + base + 8 * STRB);
                Ah[fm][2] = *(const uint32_t*)(bAh + base + 16);
                Ah[fm][3] = *(const uint32_t*)(bAh + base + 8 * STRB + 16);
                Al[fm][0] = *(const uint32_t*)(bAl + base);
                Al[fm][1] = *(const uint32_t*)(bAl + base + 8 * STRB);
                Al[fm][2] = *(const uint32_t*)(bAl + base + 16);
                Al[fm][3] = *(const uint32_t*)(bAl + base + 8 * STRB + 16);
            }
#pragma unroll
            for (int fn = 0; fn < 4; fn++) {
                uint32_t bb = (warp_n * 32 + fn * 8 + r4) * STRB + kb + c4 * 4;
                uint32_t Bh0 = *(const uint32_t*)(bBh + bb);
                uint32_t Bh1 = *(const uint32_t*)(bBh + bb + 16);
                uint32_t Bl0 = *(const uint32_t*)(bBl + bb);
                uint32_t Bl1 = *(const uint32_t*)(bBl + bb + 16);
#pragma unroll
                for (int fm = 0; fm < 2; fm++) {
                    mma_bf16(acc[fm][fn], Ah[fm], Bh0, Bh1);
                    mma_bf16(acc[fm][fn], Ah[fm], Bl0, Bl1);
                    mma_bf16(acc[fm][fn], Al[fm], Bh0, Bh1);
                }
            }
        }

        // normalize next P tile + write back (loads landed during MMAs)
        if (kt + 1 < NIT) {
#pragma unroll
            for (int i = 0; i < 4; i++) {
                av[i].x *= inv_l; av[i].y *= inv_l; av[i].z *= inv_l; av[i].w *= inv_l;
            }
#pragma unroll
            for (int i = 0; i < 4; i++) *(float4*)(Pb + (kt + 1) * 32 + i * 4) = av[i];
        }
    }

    const int cq = c4 * 2;
#pragma unroll
    for (int fm = 0; fm < 2; fm++) {
#pragma unroll
        for (int fn = 0; fn < 4; fn++) {
            int row0 = bm + warp_m * 32 + fm * 16 + r4;
            int col  = warp_n * 32 + fn * 8 + cq;
            *(float2*)(O + (size_t)row0 * EMB + col) =
                make_float2(acc[fm][fn][0], acc[fm][fn][1]);
            *(float2*)(O + (size_t)(row0 + 8) * EMB + col) =
                make_float2(acc[fm][fn][2], acc[fm][fn][3]);
        }
    }
}

// ---------------------------------------------------------------------------
extern "C" void kernel_launch(void* const* d_in, const int* in_sizes, int n_in,
                              void* d_out, int out_size)
{
    const float* x     = (const float*)d_in[0];
    const float* qkv_w = (const float*)d_in[1];
    const float* qkv_b = (const float*)d_in[2];
    const float* out_w = (const float*)d_in[3];
    const float* out_b = (const float*)d_in[4];

    float* out_proj = (float*)d_out;
    float* attn     = (float*)d_out + OUT_ELEMS;

    float* qkv = nullptr;
    float* ao  = nullptr;
    cudaGetSymbolAddress((void**)&qkv, g_qkv);
    cudaGetSymbolAddress((void**)&ao,  g_ao);

    // 1. QKV projection
    mma_gemm_bias<<<dim3(QKVF / 128, TOK / 128), 256>>>(x, qkv_w, qkv_b, qkv, QKVF, EMB);
    // 2. zero rowsums
    zero_rowsum_kernel<<<NROWS / 256, 256>>>();
    // 3. Scores + exp + rowsum atomics
    mma_scores_exp<<<dim3(SEQ / 128, SEQ / 128, BATCH * NH), 256>>>(qkv, attn);
    // 4. AV + normalize
    mma_av_norm<<<dim3(SEQ / 128, BATCH * NH), 256>>>(attn, qkv, ao);
    // 5. Output projection
    mma_gemm_bias<<<dim3(EMB / 128, TOK / 128), 256>>>(ao, out_w, out_b, out_proj, EMB, EMB);
}